// round 1
// baseline (speedup 1.0000x reference)
#include <cuda_runtime.h>
#include <math.h>

#define BB   4
#define NN   512
#define CIN  128
#define CMID 64
#define CHID 128
#define COUT 128

typedef unsigned long long ull;

// ------------------------- scratch (device globals; no allocs allowed) ----
__device__ float g_h[(size_t)BB * NN * NN * CMID];   // 256 MB: h = D@W1 + b1
__device__ float g_stats[2 * CMID];                  // sum[64], sumsq[64]
__device__ float g_bn[2 * CMID];                     // a[64], c[64]
__device__ float g_y0[BB * NN * CIN];                // A @ x
__device__ float g_y1[BB * NN * CHID];               // y0 @ Wg^T + bg (pre-BN)
__device__ float g_statsg[2 * CHID];
__device__ float g_bng[2 * CHID];

// ------------------------- f32x2 helpers ----------------------------------
__device__ __forceinline__ ull pack2(float x, float y) {
    ull r; asm("mov.b64 %0, {%1, %2};" : "=l"(r) : "f"(x), "f"(y)); return r;
}
__device__ __forceinline__ void unpack2(ull v, float &x, float &y) {
    asm("mov.b64 {%0, %1}, %2;" : "=f"(x), "=f"(y) : "l"(v));
}
__device__ __forceinline__ void fma2(ull &d, ull a, ull b) {
    asm("fma.rn.f32x2 %0, %1, %2, %0;" : "+l"(d) : "l"(a), "l"(b));
}

// ------------------------- K0: zero stat accumulators ---------------------
__global__ void k0_zero() {
    int t = threadIdx.x;
    if (t < 2 * CMID) g_stats[t] = 0.f;
    if (t < 2 * CHID) g_statsg[t] = 0.f;
}

// ------------------------- K1: pairwise |xi-xj| @ W1^T + b1, + BN stats ---
// grid (32 jt, 32 it, 4 b), 256 threads. Tile: 16x16 pairs (M=256), N=64, K=128.
__global__ __launch_bounds__(256) void k1_pair_gemm(const float* __restrict__ x,
                                                    const float* __restrict__ W1,
                                                    const float* __restrict__ b1) {
    __shared__ float xi[16][129];
    __shared__ float xj[16][129];
    __shared__ float Dk[16][260];
    __shared__ float W1k[16][68];
    __shared__ float sredS[8][64];
    __shared__ float sredQ[8][64];

    const int tid = threadIdx.x;
    const int jt = blockIdx.x, it = blockIdx.y, b = blockIdx.z;

    const float* xb = x + (size_t)b * NN * CIN;
    for (int idx = tid; idx < 16 * CIN; idx += 256) {
        int r = idx >> 7, c = idx & 127;
        xi[r][c] = xb[(size_t)(it * 16 + r) * CIN + c];
        xj[r][c] = xb[(size_t)(jt * 16 + r) * CIN + c];
    }

    const int tx = tid & 7;    // channel group (8 ch)
    const int ty = tid >> 3;   // pair group (8 pairs)
    const int ii = tid >> 4;   // D-formation pair coords
    const int jj = tid & 15;

    ull acc[8][4];
#pragma unroll
    for (int r = 0; r < 8; r++)
#pragma unroll
        for (int c = 0; c < 4; c++) acc[r][c] = 0ULL;

    __syncthreads();

    for (int k0 = 0; k0 < CIN; k0 += 16) {
        // W1 chunk: W1k[kk][o] = W1[o,k0+kk]   (W1 is [64][128] row-major)
        for (int idx = tid; idx < 16 * 64; idx += 256) {
            int kk = idx >> 6, o = idx & 63;
            W1k[kk][o] = W1[(size_t)o * CIN + k0 + kk];
        }
        // D chunk, transposed: Dk[kk][pair]
#pragma unroll
        for (int kk = 0; kk < 16; kk++)
            Dk[kk][tid] = fabsf(xi[ii][k0 + kk] - xj[jj][k0 + kk]);
        __syncthreads();

#pragma unroll
        for (int kk = 0; kk < 16; kk++) {
            float4 a0 = *(const float4*)&Dk[kk][ty * 8];
            float4 a1 = *(const float4*)&Dk[kk][ty * 8 + 4];
            float4 w0 = *(const float4*)&W1k[kk][tx * 8];
            float4 w1 = *(const float4*)&W1k[kk][tx * 8 + 4];
            ull wv0 = pack2(w0.x, w0.y), wv1 = pack2(w0.z, w0.w);
            ull wv2 = pack2(w1.x, w1.y), wv3 = pack2(w1.z, w1.w);
            float av[8] = {a0.x, a0.y, a0.z, a0.w, a1.x, a1.y, a1.z, a1.w};
#pragma unroll
            for (int r = 0; r < 8; r++) {
                ull ad = pack2(av[r], av[r]);
                fma2(acc[r][0], ad, wv0);
                fma2(acc[r][1], ad, wv1);
                fma2(acc[r][2], ad, wv2);
                fma2(acc[r][3], ad, wv3);
            }
        }
        __syncthreads();
    }

    // epilogue: bias, stats, store h
    float bias[8];
#pragma unroll
    for (int c = 0; c < 8; c++) bias[c] = b1[tx * 8 + c];

    float csum[8], csq[8];
#pragma unroll
    for (int c = 0; c < 8; c++) { csum[c] = 0.f; csq[c] = 0.f; }

    const int gi = it * 16 + (ty >> 1);
    const int gj = jt * 16 + (ty & 1) * 8;
    const size_t rowbase = (((size_t)b * NN + gi) * NN + gj) * CMID + tx * 8;

#pragma unroll
    for (int r = 0; r < 8; r++) {
        float v[8];
        unpack2(acc[r][0], v[0], v[1]);
        unpack2(acc[r][1], v[2], v[3]);
        unpack2(acc[r][2], v[4], v[5]);
        unpack2(acc[r][3], v[6], v[7]);
#pragma unroll
        for (int c = 0; c < 8; c++) {
            v[c] += bias[c];
            csum[c] += v[c];
            csq[c] += v[c] * v[c];
        }
        float4 o0 = make_float4(v[0], v[1], v[2], v[3]);
        float4 o1 = make_float4(v[4], v[5], v[6], v[7]);
        *(float4*)&g_h[rowbase + (size_t)r * CMID]     = o0;
        *(float4*)&g_h[rowbase + (size_t)r * CMID + 4] = o1;
    }

    // reduce over ty within warp (lanes with same tx: stride 8)
#pragma unroll
    for (int c = 0; c < 8; c++) {
        csum[c] += __shfl_down_sync(0xffffffffu, csum[c], 8);
        csq[c]  += __shfl_down_sync(0xffffffffu, csq[c], 8);
        csum[c] += __shfl_down_sync(0xffffffffu, csum[c], 16);
        csq[c]  += __shfl_down_sync(0xffffffffu, csq[c], 16);
    }
    const int lane = tid & 31, wrp = tid >> 5;
    if (lane < 8) {
#pragma unroll
        for (int c = 0; c < 8; c++) {
            sredS[wrp][lane * 8 + c] = csum[c];
            sredQ[wrp][lane * 8 + c] = csq[c];
        }
    }
    __syncthreads();
    if (tid < 64) {
        float s = 0.f, q = 0.f;
#pragma unroll
        for (int w = 0; w < 8; w++) { s += sredS[w][tid]; q += sredQ[w][tid]; }
        atomicAdd(&g_stats[tid], s);
        atomicAdd(&g_stats[64 + tid], q);
    }
}

// ------------------------- K2: finalize BN2d ------------------------------
__global__ void k2_bn2d(const float* __restrict__ g1, const float* __restrict__ be1) {
    int c = threadIdx.x;  // 64
    const float invcnt = 1.0f / (float)((size_t)BB * NN * NN);
    float m = g_stats[c] * invcnt;
    float v = g_stats[64 + c] * invcnt - m * m;
    float a = g1[c] / sqrtf(v + 1e-5f);
    g_bn[c] = a;
    g_bn[64 + c] = be1[c] - m * a;
}

// ------------------------- K3: s = lrelu(BN(h))@W2 + b2, mask, softmax, y0 = A@x
// grid (512 i, 4 b), 128 threads (one block per adjacency row)
__global__ __launch_bounds__(128) void k3_softmax_agg(const float* __restrict__ x,
                                                      const int* __restrict__ A_init,
                                                      const float* __restrict__ W2,
                                                      const float* __restrict__ b2) {
    __shared__ float sA[512];
    __shared__ float sa[64], sc[64], sw[64];
    __shared__ float rbuf[8];

    const int tid = threadIdx.x;
    const int i = blockIdx.x, b = blockIdx.y;
    if (tid < 64) { sa[tid] = g_bn[tid]; sc[tid] = g_bn[64 + tid]; sw[tid] = W2[tid]; }
    __syncthreads();

    const float b2v = b2[0];
    const float* hrow = g_h + ((size_t)b * NN + i) * NN * CMID;
    const int* arow = A_init + ((size_t)b * NN + i) * NN;

#pragma unroll
    for (int q = 0; q < 4; q++) {
        int j = q * 128 + tid;
        const float* hp = hrow + (size_t)j * CMID;
        float s = b2v;
#pragma unroll
        for (int o = 0; o < 64; o += 4) {
            float4 h4 = *(const float4*)(hp + o);
            float v0 = h4.x * sa[o]     + sc[o];
            float v1 = h4.y * sa[o + 1] + sc[o + 1];
            float v2 = h4.z * sa[o + 2] + sc[o + 2];
            float v3 = h4.w * sa[o + 3] + sc[o + 3];
            v0 = v0 > 0.f ? v0 : 0.01f * v0;
            v1 = v1 > 0.f ? v1 : 0.01f * v1;
            v2 = v2 > 0.f ? v2 : 0.01f * v2;
            v3 = v3 > 0.f ? v3 : 0.01f * v3;
            s += v0 * sw[o] + v1 * sw[o + 1] + v2 * sw[o + 2] + v3 * sw[o + 3];
        }
        sA[j] = (arow[j] > 0) ? s : -9e15f;
    }
    __syncthreads();

    float m = -3.0e38f;
#pragma unroll
    for (int q = 0; q < 4; q++) m = fmaxf(m, sA[q * 128 + tid]);
#pragma unroll
    for (int off = 16; off > 0; off >>= 1) m = fmaxf(m, __shfl_xor_sync(0xffffffffu, m, off));
    if ((tid & 31) == 0) rbuf[tid >> 5] = m;
    __syncthreads();
    m = fmaxf(fmaxf(rbuf[0], rbuf[1]), fmaxf(rbuf[2], rbuf[3]));

    float ps = 0.f;
#pragma unroll
    for (int q = 0; q < 4; q++) {
        int j = q * 128 + tid;
        float p = __expf(sA[j] - m);
        sA[j] = p;
        ps += p;
    }
#pragma unroll
    for (int off = 16; off > 0; off >>= 1) ps += __shfl_xor_sync(0xffffffffu, ps, off);
    if ((tid & 31) == 0) rbuf[4 + (tid >> 5)] = ps;
    __syncthreads();
    float inv = 1.0f / (rbuf[4] + rbuf[5] + rbuf[6] + rbuf[7]);
#pragma unroll
    for (int q = 0; q < 4; q++) sA[q * 128 + tid] *= inv;
    __syncthreads();

    // y0[b,i,c] = sum_j A[j] * x[b,j,c]
    const float* xb = x + (size_t)b * NN * CIN;
    float accv = 0.f;
#pragma unroll 8
    for (int j = 0; j < 512; j++) accv += sA[j] * xb[(size_t)j * CIN + tid];
    g_y0[((size_t)b * NN + i) * CIN + tid] = accv;
}

// ------------------------- K4: y1 = y0 @ Wg^T + bg, + BN1d stats ----------
// 64 blocks x 256 threads; block covers 32 rows x 128 cols
__global__ __launch_bounds__(256) void k4_fc_g(const float* __restrict__ Wg,
                                               const float* __restrict__ bg) {
    __shared__ float ys[32][129];
    __shared__ float s0[128], q0[128];
    const int tid = threadIdx.x;
    const int rb = blockIdx.x;
    for (int idx = tid; idx < 32 * 128; idx += 256) {
        int r = idx >> 7, c = idx & 127;
        ys[r][c] = g_y0[(size_t)(rb * 32 + r) * 128 + c];
    }
    __syncthreads();
    const int c = tid & 127, half = tid >> 7;
    float acc[16];
    const float bgv = bg[c];
#pragma unroll
    for (int r = 0; r < 16; r++) acc[r] = bgv;
    const float* wrow = Wg + (size_t)c * 128;
    for (int k = 0; k < 128; k++) {
        float w = __ldg(&wrow[k]);
#pragma unroll
        for (int r = 0; r < 16; r++) acc[r] += ys[half * 16 + r][k] * w;
    }
    float s = 0.f, q = 0.f;
#pragma unroll
    for (int r = 0; r < 16; r++) {
        float v = acc[r];
        s += v; q += v * v;
        g_y1[(size_t)(rb * 32 + half * 16 + r) * 128 + c] = v;
    }
    if (half == 0) { s0[c] = s; q0[c] = q; }
    __syncthreads();
    if (half == 1) {
        atomicAdd(&g_statsg[c], s + s0[c]);
        atomicAdd(&g_statsg[128 + c], q + q0[c]);
    }
}

// ------------------------- K5: finalize BN1d ------------------------------
__global__ void k5_bn1d(const float* __restrict__ gg, const float* __restrict__ beg) {
    int c = threadIdx.x;  // 128
    const float invcnt = 1.0f / (float)(BB * NN);
    float m = g_statsg[c] * invcnt;
    float v = g_statsg[128 + c] * invcnt - m * m;
    float a = gg[c] / sqrtf(v + 1e-5f);
    g_bng[c] = a;
    g_bng[128 + c] = beg[c] - m * a;
}

// ------------------------- K6: out = [x, lrelu(BN(y1))] @ Wt^T + bt -------
__global__ __launch_bounds__(256) void k6_trans(const float* __restrict__ x,
                                                const float* __restrict__ Wt,
                                                const float* __restrict__ bt,
                                                float* __restrict__ out) {
    __shared__ float zs[32][257];
    const int tid = threadIdx.x;
    const int rb = blockIdx.x;
    for (int idx = tid; idx < 32 * 256; idx += 256) {
        int r = idx >> 8, k = idx & 255;
        int row = rb * 32 + r;
        float v;
        if (k < 128) {
            v = x[(size_t)row * 128 + k];
        } else {
            int hch = k - 128;
            float y = g_y1[(size_t)row * 128 + hch];
            y = y * g_bng[hch] + g_bng[128 + hch];
            v = y > 0.f ? y : 0.01f * y;
        }
        zs[r][k] = v;
    }
    __syncthreads();
    const int c = tid & 127, half = tid >> 7;
    float acc[16];
    const float btv = bt[c];
#pragma unroll
    for (int r = 0; r < 16; r++) acc[r] = btv;
    const float* wrow = Wt + (size_t)c * 256;
    for (int k = 0; k < 256; k++) {
        float w = __ldg(&wrow[k]);
#pragma unroll
        for (int r = 0; r < 16; r++) acc[r] += zs[half * 16 + r][k] * w;
    }
#pragma unroll
    for (int r = 0; r < 16; r++)
        out[(size_t)(rb * 32 + half * 16 + r) * 128 + c] = acc[r];
}

// ------------------------- launch -----------------------------------------
extern "C" void kernel_launch(void* const* d_in, const int* in_sizes, int n_in,
                              void* d_out, int out_size) {
    const float* x      = (const float*)d_in[0];
    const int*   A_init = (const int*)d_in[1];
    const float* W1     = (const float*)d_in[2];
    const float* b1     = (const float*)d_in[3];
    const float* g1     = (const float*)d_in[4];
    const float* be1    = (const float*)d_in[5];
    const float* W2     = (const float*)d_in[6];
    const float* b2     = (const float*)d_in[7];
    const float* Wg     = (const float*)d_in[8];
    const float* bg     = (const float*)d_in[9];
    const float* gg     = (const float*)d_in[10];
    const float* beg    = (const float*)d_in[11];
    const float* Wt     = (const float*)d_in[12];
    const float* bt     = (const float*)d_in[13];
    float* out = (float*)d_out;

    k0_zero<<<1, 256>>>();
    dim3 g1grid(32, 32, 4);
    k1_pair_gemm<<<g1grid, 256>>>(x, W1, b1);
    k2_bn2d<<<1, 64>>>(g1, be1);
    dim3 g3grid(512, 4);
    k3_softmax_agg<<<g3grid, 128>>>(x, A_init, W2, b2);
    k4_fc_g<<<64, 256>>>(Wg, bg);
    k5_bn1d<<<1, 128>>>(gg, beg);
    k6_trans<<<64, 256>>>(x, Wt, bt, out);
}

// round 4
// speedup vs baseline: 1.5744x; 1.5744x over previous
#include <cuda_runtime.h>
#include <math.h>
#include <cstdint>

#define BB   4
#define NN   512
#define CIN  128
#define CMID 64

// ------------------------- scratch (device globals) ------------------------
__device__ float g_h[(size_t)BB * NN * NN * CMID];   // 256 MB h
__device__ float g_stats[32 * 128];                  // 32 slots x (sum64|sq64)
__device__ float g_bn[2 * CMID];
__device__ float g_y0[BB * NN * CIN];
__device__ float g_y1[BB * NN * 128];
__device__ float g_statsg[2 * 128];
__device__ float g_bng[2 * 128];

// ------------------------- mma.sync tf32 helper ----------------------------
__device__ __forceinline__ void mma_tf32(float* d, const uint32_t* a,
                                         uint32_t b0, uint32_t b1) {
    asm volatile(
        "mma.sync.aligned.m16n8k8.row.col.f32.tf32.tf32.f32 "
        "{%0,%1,%2,%3}, {%4,%5,%6,%7}, {%8,%9}, {%0,%1,%2,%3};"
        : "+f"(d[0]), "+f"(d[1]), "+f"(d[2]), "+f"(d[3])
        : "r"(a[0]), "r"(a[1]), "r"(a[2]), "r"(a[3]), "r"(b0), "r"(b1));
}
__device__ __forceinline__ uint32_t cvt_tf32(float v) {
    uint32_t r; asm("cvt.rna.tf32.f32 %0, %1;" : "=r"(r) : "f"(v)); return r;
}

// ------------------------- K0: zero stat accumulators ---------------------
__global__ void k0_zero() {
    int t = threadIdx.x;
    for (int i = t; i < 32 * 128; i += 256) g_stats[i] = 0.f;
    if (t < 256) g_statsg[t] = 0.f;
}

// ------------------------- K1: pairwise GEMM via HMMA tf32 3x-split -------
// grid (4 jt, 512 i, 4 b), 128 threads (4 warps).
// Block: fixed i; M = 128 j-pairs, N = 64 ch, K = 128. Warp = 32 j rows.
#define OFF_XI   0                       // 128 f
#define OFF_B1   512                     // 64 f
#define OFF_SRED 768                     // 4*128 f
#define OFF_XJS  2816                    // 128 rows * 36 f (one 32-k chunk)
#define OFF_BHI  21248                   // 8192 u32  (W1 hi, swizzled)
#define OFF_BLO  54016                   // 8192 f    (W1 lo, swizzled)
#define K1_SMEM  86784

// swizzled W1 word offset: o in [0,64), k in [0,128)
__device__ __forceinline__ int boff_w1(int o, int k) {
    return (o >> 3) * 1024 + k * 8 + ((o & 7) ^ (k & 7) ^ ((k >> 3) & 7));
}

__global__ __launch_bounds__(128) void k1_pair_gemm(const float* __restrict__ x,
                                                    const float* __restrict__ W1,
                                                    const float* __restrict__ b1) {
    extern __shared__ char smem[];
    float*    xi_s = (float*)(smem + OFF_XI);
    float*    b1s  = (float*)(smem + OFF_B1);
    float*    sred = (float*)(smem + OFF_SRED);
    float*    xjS  = (float*)(smem + OFF_XJS);
    uint32_t* Bhi  = (uint32_t*)(smem + OFF_BHI);
    float*    Blo  = (float*)(smem + OFF_BLO);

    const int tid = threadIdx.x;
    const int w = tid >> 5, l = tid & 31;
    const int lr = l >> 2, lc = l & 3;
    const int jt = blockIdx.x, i = blockIdx.y, b = blockIdx.z;
    const int j0 = jt * 128;
    const float* xb = x + (size_t)b * NN * CIN;

    // stage xi row, bias
    xi_s[tid] = xb[(size_t)i * CIN + tid];
    if (tid < 64) b1s[tid] = b1[tid];

    // stage W1 hi/lo (swizzled, conflict-free store & frag-read)
    for (int it = 0; it < 64; it++) {
        float wv = W1[it * 128 + tid];
        uint32_t hb = cvt_tf32(wv);
        int off = boff_w1(it, tid);
        Bhi[off] = hb;
        Blo[off] = wv - __uint_as_float(hb);
    }

    // accumulators: d[mt][nt][4]
    float d[2][8][4];
#pragma unroll
    for (int mt = 0; mt < 2; mt++)
#pragma unroll
        for (int nt = 0; nt < 8; nt++)
#pragma unroll
            for (int r = 0; r < 4; r++) d[mt][nt][r] = 0.f;

    for (int kc = 0; kc < 128; kc += 32) {
        __syncthreads();
        // stage xj chunk: xjS[row][kk], pitch 36 (conflict-free frag reads)
        for (int it = 0; it < 32; it++) {
            int row = it * 4 + (tid >> 5);
            int kk = tid & 31;
            xjS[row * 36 + kk] = xb[(size_t)(j0 + row) * CIN + kc + kk];
        }
        __syncthreads();

        for (int ks = 0; ks < 4; ks++) {
            const int k0 = ks * 8;
            const float xv0 = xi_s[kc + k0 + lc];
            const float xv1 = xi_s[kc + k0 + 4 + lc];

            uint32_t ahi[2][4], alo[2][4];
#pragma unroll
            for (int mt = 0; mt < 2; mt++) {
                const int r0 = (w * 32 + mt * 16 + lr) * 36 + k0 + lc;
                float v0 = fabsf(xv0 - xjS[r0]);
                float v1 = fabsf(xv0 - xjS[r0 + 8 * 36]);
                float v2 = fabsf(xv1 - xjS[r0 + 4]);
                float v3 = fabsf(xv1 - xjS[r0 + 8 * 36 + 4]);
                uint32_t h0 = cvt_tf32(v0), h1 = cvt_tf32(v1);
                uint32_t h2 = cvt_tf32(v2), h3 = cvt_tf32(v3);
                ahi[mt][0] = h0; ahi[mt][1] = h1; ahi[mt][2] = h2; ahi[mt][3] = h3;
                alo[mt][0] = __float_as_uint(v0 - __uint_as_float(h0));
                alo[mt][1] = __float_as_uint(v1 - __uint_as_float(h1));
                alo[mt][2] = __float_as_uint(v2 - __uint_as_float(h2));
                alo[mt][3] = __float_as_uint(v3 - __uint_as_float(h3));
            }

            // B fragment: b0 = W1[n=nt*8+lr][k=kg+lc], b1 = k+4 (k index is lane-dep!)
            const int kg = kc + k0;
            const int C = (kg >> 3) & 7;
            const int s0 = (lr ^ lc ^ C);
            const int base0 = (kg + lc) * 8 + s0;
            const int base1 = (kg + 4 + lc) * 8 + (s0 ^ 4);
#pragma unroll
            for (int nt = 0; nt < 8; nt++) {
                const int nb = nt * 1024;
                uint32_t bh0 = Bhi[nb + base0];
                uint32_t bh1 = Bhi[nb + base1];
                uint32_t bl0 = __float_as_uint(Blo[nb + base0]);
                uint32_t bl1 = __float_as_uint(Blo[nb + base1]);
#pragma unroll
                for (int mt = 0; mt < 2; mt++) {
                    mma_tf32(d[mt][nt], ahi[mt], bh0, bh1);
                    mma_tf32(d[mt][nt], alo[mt], bh0, bh1);
                    mma_tf32(d[mt][nt], ahi[mt], bl0, bl1);
                }
            }
        }
    }

    // ---- epilogue: bias, store h, channel stats
    float ssum[16], ssq[16];
#pragma unroll
    for (int s = 0; s < 16; s++) { ssum[s] = 0.f; ssq[s] = 0.f; }

    const size_t bi = (size_t)b * NN + i;
#pragma unroll
    for (int mt = 0; mt < 2; mt++) {
        const size_t base0 = (bi * NN + j0 + w * 32 + mt * 16 + lr) * CMID;
        const size_t base1 = base0 + 8 * CMID;
#pragma unroll
        for (int nt = 0; nt < 8; nt++) {
            const int ch = nt * 8 + lc * 2;
            float v0 = d[mt][nt][0] + b1s[ch];
            float v1 = d[mt][nt][1] + b1s[ch + 1];
            float v2 = d[mt][nt][2] + b1s[ch];
            float v3 = d[mt][nt][3] + b1s[ch + 1];
            *(float2*)&g_h[base0 + ch] = make_float2(v0, v1);
            *(float2*)&g_h[base1 + ch] = make_float2(v2, v3);
            ssum[nt * 2]     += v0 + v2;
            ssq[nt * 2]      += v0 * v0 + v2 * v2;
            ssum[nt * 2 + 1] += v1 + v3;
            ssq[nt * 2 + 1]  += v1 * v1 + v3 * v3;
        }
    }
    // butterfly over lanes with same lc (offsets 4, 8, 16)
#pragma unroll
    for (int s = 0; s < 16; s++) {
#pragma unroll
        for (int off = 4; off <= 16; off <<= 1) {
            ssum[s] += __shfl_xor_sync(0xffffffffu, ssum[s], off);
            ssq[s]  += __shfl_xor_sync(0xffffffffu, ssq[s], off);
        }
    }
    if (l < 4) {
#pragma unroll
        for (int nt = 0; nt < 8; nt++) {
            sred[w * 128 + nt * 8 + l * 2]      = ssum[nt * 2];
            sred[w * 128 + nt * 8 + l * 2 + 1]  = ssum[nt * 2 + 1];
            sred[w * 128 + 64 + nt * 8 + l * 2]     = ssq[nt * 2];
            sred[w * 128 + 64 + nt * 8 + l * 2 + 1] = ssq[nt * 2 + 1];
        }
    }
    __syncthreads();
    if (tid < 128) {
        float a = sred[tid] + sred[128 + tid] + sred[256 + tid] + sred[384 + tid];
        int slot = (blockIdx.x + (blockIdx.y << 2) + blockIdx.z) & 31;
        atomicAdd(&g_stats[slot * 128 + tid], a);
    }
}

// ------------------------- K2: finalize BN2d ------------------------------
__global__ void k2_bn2d(const float* __restrict__ g1, const float* __restrict__ be1) {
    int c = threadIdx.x;  // 64
    float s = 0.f, q = 0.f;
    for (int sl = 0; sl < 32; sl++) { s += g_stats[sl * 128 + c]; q += g_stats[sl * 128 + 64 + c]; }
    const float invcnt = 1.0f / (float)((size_t)BB * NN * NN);
    float m = s * invcnt;
    float v = q * invcnt - m * m;
    float a = g1[c] / sqrtf(v + 1e-5f);
    g_bn[c] = a;
    g_bn[64 + c] = be1[c] - m * a;
}

// ------------------------- K3: scores + softmax + A@x ---------------------
// grid (512 i, 4 b), 256 threads. 16 lanes cooperate per j-row (coalesced h).
__global__ __launch_bounds__(256) void k3_softmax_agg(const float* __restrict__ x,
                                                      const int* __restrict__ A_init,
                                                      const float* __restrict__ W2,
                                                      const float* __restrict__ b2) {
    __shared__ float sA[512];
    __shared__ float sa[64], sc[64], sw[64];
    __shared__ float red[16];
    __shared__ float ytmp[128];

    const int tid = threadIdx.x;
    const int i = blockIdx.x, b = blockIdx.y;
    if (tid < 64) { sa[tid] = g_bn[tid]; sc[tid] = g_bn[64 + tid]; sw[tid] = W2[tid]; }
    __syncthreads();

    const int w = tid >> 5, l = tid & 31, g = l >> 4, q = l & 15;
    const float* hrow = g_h + ((size_t)b * NN + i) * NN * CMID;
    const int* arow = A_init + ((size_t)b * NN + i) * NN;
    const float b2v = b2[0];
    const int o = q * 4;
    const float a0 = sa[o], a1 = sa[o + 1], a2 = sa[o + 2], a3 = sa[o + 3];
    const float c0 = sc[o], c1 = sc[o + 1], c2 = sc[o + 2], c3 = sc[o + 3];
    const float w0 = sw[o], w1 = sw[o + 1], w2v = sw[o + 2], w3 = sw[o + 3];

#pragma unroll 4
    for (int t = 0; t < 32; t++) {
        int j = t * 16 + w * 2 + g;
        float4 h4 = *(const float4*)(hrow + (size_t)j * CMID + o);
        float z0 = h4.x * a0 + c0, z1 = h4.y * a1 + c1;
        float z2 = h4.z * a2 + c2, z3 = h4.w * a3 + c3;
        z0 = fmaxf(z0, 0.f) + 0.01f * fminf(z0, 0.f);
        z1 = fmaxf(z1, 0.f) + 0.01f * fminf(z1, 0.f);
        z2 = fmaxf(z2, 0.f) + 0.01f * fminf(z2, 0.f);
        z3 = fmaxf(z3, 0.f) + 0.01f * fminf(z3, 0.f);
        float p = z0 * w0 + z1 * w1 + z2 * w2v + z3 * w3;
        p += __shfl_down_sync(0xffffffffu, p, 8, 16);
        p += __shfl_down_sync(0xffffffffu, p, 4, 16);
        p += __shfl_down_sync(0xffffffffu, p, 2, 16);
        p += __shfl_down_sync(0xffffffffu, p, 1, 16);
        if (q == 0) sA[j] = (arow[j] > 0) ? (p + b2v) : -9e15f;
    }
    __syncthreads();

    // softmax over 512
    float m0 = fmaxf(sA[tid], sA[tid + 256]);
#pragma unroll
    for (int off = 16; off > 0; off >>= 1) m0 = fmaxf(m0, __shfl_xor_sync(0xffffffffu, m0, off));
    if (l == 0) red[w] = m0;
    __syncthreads();
    float m = red[0];
#pragma unroll
    for (int k = 1; k < 8; k++) m = fmaxf(m, red[k]);

    float e0 = __expf(sA[tid] - m), e1 = __expf(sA[tid + 256] - m);
    float ps = e0 + e1;
#pragma unroll
    for (int off = 16; off > 0; off >>= 1) ps += __shfl_xor_sync(0xffffffffu, ps, off);
    if (l == 0) red[8 + w] = ps;
    sA[tid] = e0; sA[tid + 256] = e1;
    __syncthreads();
    float tot = red[8] + red[9] + red[10] + red[11] + red[12] + red[13] + red[14] + red[15];
    float inv = 1.0f / tot;
    sA[tid] *= inv; sA[tid + 256] *= inv;
    __syncthreads();

    // y0[b,i,c] = sum_j A[j] x[b,j,c]
    const int c = tid & 127, hf = tid >> 7;
    const float* xp = x + ((size_t)b * NN + hf * 256) * CIN + c;
    const float* aP = &sA[hf * 256];
    float acc = 0.f;
#pragma unroll 8
    for (int j = 0; j < 256; j++) acc += aP[j] * xp[(size_t)j * CIN];
    if (hf == 1) ytmp[c] = acc;
    __syncthreads();
    if (hf == 0) g_y0[((size_t)b * NN + i) * CIN + c] = acc + ytmp[c];
}

// ------------------------- K4: y1 = y0 @ Wg^T + bg, + BN1d stats ----------
__global__ __launch_bounds__(256) void k4_fc_g(const float* __restrict__ Wg,
                                               const float* __restrict__ bg) {
    __shared__ float ys[32][129];
    __shared__ float s0[128], q0[128];
    const int tid = threadIdx.x;
    const int rb = blockIdx.x;
    for (int idx = tid; idx < 32 * 128; idx += 256) {
        int r = idx >> 7, c = idx & 127;
        ys[r][c] = g_y0[(size_t)(rb * 32 + r) * 128 + c];
    }
    __syncthreads();
    const int c = tid & 127, half = tid >> 7;
    float acc[16];
    const float bgv = bg[c];
#pragma unroll
    for (int r = 0; r < 16; r++) acc[r] = bgv;
    const float* wrow = Wg + (size_t)c * 128;
    for (int k = 0; k < 128; k++) {
        float w = __ldg(&wrow[k]);
#pragma unroll
        for (int r = 0; r < 16; r++) acc[r] += ys[half * 16 + r][k] * w;
    }
    float s = 0.f, q = 0.f;
#pragma unroll
    for (int r = 0; r < 16; r++) {
        float v = acc[r];
        s += v; q += v * v;
        g_y1[(size_t)(rb * 32 + half * 16 + r) * 128 + c] = v;
    }
    if (half == 0) { s0[c] = s; q0[c] = q; }
    __syncthreads();
    if (half == 1) {
        atomicAdd(&g_statsg[c], s + s0[c]);
        atomicAdd(&g_statsg[128 + c], q + q0[c]);
    }
}

// ------------------------- K5: finalize BN1d ------------------------------
__global__ void k5_bn1d(const float* __restrict__ gg, const float* __restrict__ beg) {
    int c = threadIdx.x;  // 128
    const float invcnt = 1.0f / (float)(BB * NN);
    float m = g_statsg[c] * invcnt;
    float v = g_statsg[128 + c] * invcnt - m * m;
    float a = gg[c] / sqrtf(v + 1e-5f);
    g_bng[c] = a;
    g_bng[128 + c] = beg[c] - m * a;
}

// ------------------------- K6: out = [x, lrelu(BN(y1))] @ Wt^T + bt -------
__global__ __launch_bounds__(256) void k6_trans(const float* __restrict__ x,
                                                const float* __restrict__ Wt,
                                                const float* __restrict__ bt,
                                                float* __restrict__ out) {
    __shared__ float zs[32][257];
    const int tid = threadIdx.x;
    const int rb = blockIdx.x;
    for (int idx = tid; idx < 32 * 256; idx += 256) {
        int r = idx >> 8, k = idx & 255;
        int row = rb * 32 + r;
        float v;
        if (k < 128) {
            v = x[(size_t)row * 128 + k];
        } else {
            int hch = k - 128;
            float y = g_y1[(size_t)row * 128 + hch];
            y = y * g_bng[hch] + g_bng[128 + hch];
            v = y > 0.f ? y : 0.01f * y;
        }
        zs[r][k] = v;
    }
    __syncthreads();
    const int c = tid & 127, half = tid >> 7;
    float acc[16];
    const float btv = bt[c];
#pragma unroll
    for (int r = 0; r < 16; r++) acc[r] = btv;
    const float* wrow = Wt + (size_t)c * 256;
    for (int k = 0; k < 256; k++) {
        float w = __ldg(&wrow[k]);
#pragma unroll
        for (int r = 0; r < 16; r++) acc[r] += zs[half * 16 + r][k] * w;
    }
#pragma unroll
    for (int r = 0; r < 16; r++)
        out[(size_t)(rb * 32 + half * 16 + r) * 128 + c] = acc[r];
}

// ------------------------- launch -----------------------------------------
extern "C" void kernel_launch(void* const* d_in, const int* in_sizes, int n_in,
                              void* d_out, int out_size) {
    const float* x      = (const float*)d_in[0];
    const int*   A_init = (const int*)d_in[1];
    const float* W1     = (const float*)d_in[2];
    const float* b1     = (const float*)d_in[3];
    const float* g1     = (const float*)d_in[4];
    const float* be1    = (const float*)d_in[5];
    const float* W2     = (const float*)d_in[6];
    const float* b2     = (const float*)d_in[7];
    const float* Wg     = (const float*)d_in[8];
    const float* bg     = (const float*)d_in[9];
    const float* gg     = (const float*)d_in[10];
    const float* beg    = (const float*)d_in[11];
    const float* Wt     = (const float*)d_in[12];
    const float* bt     = (const float*)d_in[13];
    float* out = (float*)d_out;

    cudaFuncSetAttribute(k1_pair_gemm, cudaFuncAttributeMaxDynamicSharedMemorySize, K1_SMEM);

    k0_zero<<<1, 256>>>();
    dim3 g1grid(4, 512, 4);
    k1_pair_gemm<<<g1grid, 128, K1_SMEM>>>(x, W1, b1);
    k2_bn2d<<<1, 64>>>(g1, be1);
    dim3 g3grid(512, 4);
    k3_softmax_agg<<<g3grid, 256>>>(x, A_init, W2, b2);
    k4_fc_g<<<64, 256>>>(Wg, bg);
    k5_bn1d<<<1, 128>>>(gg, beg);
    k6_trans<<<64, 256>>>(x, Wt, bt, out);
}

// round 5
// speedup vs baseline: 1.9257x; 1.2231x over previous
#include <cuda_runtime.h>
#include <cuda_bf16.h>
#include <math.h>
#include <cstdint>

#define BB   4
#define NN   512
#define CIN  128
#define CMID 64

// ------------------------- scratch (device globals) ------------------------
__device__ float g_h[(size_t)BB * NN * NN * CMID];   // 256 MB h
__device__ float g_A[(size_t)BB * NN * NN];          // 4 MB softmax probs
__device__ float g_stats[32 * 128];
__device__ float g_bn[2 * CMID];
__device__ float g_y0[BB * NN * CIN];
__device__ float g_y1[BB * NN * 128];
__device__ float g_statsg[2 * 128];
__device__ float g_bng[2 * 128];

// ------------------------- mma.sync bf16 helpers ---------------------------
__device__ __forceinline__ void mma_bf16(float* d, const uint32_t* a,
                                         uint32_t b0, uint32_t b1) {
    asm volatile(
        "mma.sync.aligned.m16n8k16.row.col.f32.bf16.bf16.f32 "
        "{%0,%1,%2,%3}, {%4,%5,%6,%7}, {%8,%9}, {%0,%1,%2,%3};"
        : "+f"(d[0]), "+f"(d[1]), "+f"(d[2]), "+f"(d[3])
        : "r"(a[0]), "r"(a[1]), "r"(a[2]), "r"(a[3]), "r"(b0), "r"(b1));
}
// split (v0,v1) pair -> packed bf16x2 hi and lo parts (lo half = v0, k-even)
__device__ __forceinline__ void split2(float v0, float v1, uint32_t &hi, uint32_t &lo) {
    float h0 = __bfloat162float(__float2bfloat16(v0));
    float h1 = __bfloat162float(__float2bfloat16(v1));
    asm("cvt.rn.bf16x2.f32 %0, %1, %2;" : "=r"(hi) : "f"(h1), "f"(h0));
    float l0 = v0 - h0, l1 = v1 - h1;
    asm("cvt.rn.bf16x2.f32 %0, %1, %2;" : "=r"(lo) : "f"(l1), "f"(l0));
}

// ------------------------- K0: zero stat accumulators ---------------------
__global__ void k0_zero() {
    int t = threadIdx.x;
    for (int i = t; i < 32 * 128; i += 256) g_stats[i] = 0.f;
    if (t < 256) g_statsg[t] = 0.f;
}

// ------------------------- K1: pairwise GEMM via HMMA bf16 3x-split -------
// grid (4 jt, 512 i, 4 b), 128 threads (4 warps).
// Block: fixed i; M = 128 j-pairs, N = 64 ch, K = 128. Warp = 32 j rows.
#define OFF_XI   0                       // 128 f
#define OFF_B1   512                     // 64 f
#define OFF_SRED 768                     // 4*128 f
#define OFF_XJS  2816                    // 128 rows * 36 f (one 32-k chunk)
#define OFF_WHI  21248                   // 4096 u32 (W1 hi bf16x2, swizzled)
#define OFF_WLO  37632                   // 4096 u32 (W1 lo bf16x2, swizzled)
#define K1_SMEM  54016

__global__ __launch_bounds__(128) void k1_pair_gemm(const float* __restrict__ x,
                                                    const float* __restrict__ W1,
                                                    const float* __restrict__ b1) {
    extern __shared__ char smem[];
    float*    xi_s = (float*)(smem + OFF_XI);
    float*    b1s  = (float*)(smem + OFF_B1);
    float*    sred = (float*)(smem + OFF_SRED);
    float*    xjS  = (float*)(smem + OFF_XJS);
    uint32_t* Whi  = (uint32_t*)(smem + OFF_WHI);
    uint32_t* Wlo  = (uint32_t*)(smem + OFF_WLO);

    const int tid = threadIdx.x;
    const int w = tid >> 5, l = tid & 31;
    const int lr = l >> 2, lc = l & 3;
    const int jt = blockIdx.x, i = blockIdx.y, b = blockIdx.z;
    const int j0 = jt * 128;
    const float* xb = x + (size_t)b * NN * CIN;

    xi_s[tid] = xb[(size_t)i * CIN + tid];
    if (tid < 64) b1s[tid] = b1[tid];

    // stage W1 as bf16x2 hi/lo pairs, swizzled: word index o*64 + (kp ^ ((o&7)<<2))
    for (int idx = tid; idx < 4096; idx += 128) {
        int o = idx >> 6, kp = idx & 63;
        float2 v = *(const float2*)&W1[o * 128 + kp * 2];
        uint32_t hi, lo;
        split2(v.x, v.y, hi, lo);
        int off = o * 64 + (kp ^ ((o & 7) << 2));
        Whi[off] = hi;
        Wlo[off] = lo;
    }

    float d[2][8][4];
#pragma unroll
    for (int mt = 0; mt < 2; mt++)
#pragma unroll
        for (int nt = 0; nt < 8; nt++)
#pragma unroll
            for (int r = 0; r < 4; r++) d[mt][nt][r] = 0.f;

    for (int kc = 0; kc < 128; kc += 32) {
        __syncthreads();
        for (int it = 0; it < 32; it++) {
            int row = it * 4 + (tid >> 5);
            int kk = tid & 31;
            xjS[row * 36 + kk] = xb[(size_t)(j0 + row) * CIN + kc + kk];
        }
        __syncthreads();

#pragma unroll
        for (int ks = 0; ks < 2; ks++) {
            const int k0 = ks * 16;          // local within 32-chunk
            const int kg = kc + k0;          // global k base of this k16 step
            const float2 xv0 = *(const float2*)&xi_s[kg + 2 * lc];
            const float2 xv1 = *(const float2*)&xi_s[kg + 8 + 2 * lc];

            uint32_t ahi[2][4], alo[2][4];
#pragma unroll
            for (int mt = 0; mt < 2; mt++) {
                const int rbase = (w * 32 + mt * 16 + lr) * 36 + k0 + 2 * lc;
                float2 j00 = *(const float2*)&xjS[rbase];            // row lr,   k grp0
                float2 j10 = *(const float2*)&xjS[rbase + 8 * 36];   // row lr+8, k grp0
                float2 j01 = *(const float2*)&xjS[rbase + 8];        // row lr,   k grp1
                float2 j11 = *(const float2*)&xjS[rbase + 8 * 36 + 8];
                split2(fabsf(xv0.x - j00.x), fabsf(xv0.y - j00.y), ahi[mt][0], alo[mt][0]);
                split2(fabsf(xv0.x - j10.x), fabsf(xv0.y - j10.y), ahi[mt][1], alo[mt][1]);
                split2(fabsf(xv1.x - j01.x), fabsf(xv1.y - j01.y), ahi[mt][2], alo[mt][2]);
                split2(fabsf(xv1.x - j11.x), fabsf(xv1.y - j11.y), ahi[mt][3], alo[mt][3]);
            }

            const int kgp = kg >> 1;          // pair index base (multiple of 8)
            const int swz = lr << 2;
            const int c0 = (kgp + lc) ^ swz;
            const int c1 = (kgp + 4 + lc) ^ swz;
#pragma unroll
            for (int nt = 0; nt < 8; nt++) {
                const int ob = (nt * 8 + lr) * 64;
                uint32_t bh0 = Whi[ob + c0];
                uint32_t bh1 = Whi[ob + c1];
                uint32_t bl0 = Wlo[ob + c0];
                uint32_t bl1 = Wlo[ob + c1];
#pragma unroll
                for (int mt = 0; mt < 2; mt++) {
                    mma_bf16(d[mt][nt], ahi[mt], bh0, bh1);
                    mma_bf16(d[mt][nt], ahi[mt], bl0, bl1);
                    mma_bf16(d[mt][nt], alo[mt], bh0, bh1);
                }
            }
        }
    }

    // ---- epilogue: bias, store h, channel stats
    float ssum[16], ssq[16];
#pragma unroll
    for (int s = 0; s < 16; s++) { ssum[s] = 0.f; ssq[s] = 0.f; }

    const size_t bi = (size_t)b * NN + i;
#pragma unroll
    for (int mt = 0; mt < 2; mt++) {
        const size_t base0 = (bi * NN + j0 + w * 32 + mt * 16 + lr) * CMID;
        const size_t base1 = base0 + 8 * CMID;
#pragma unroll
        for (int nt = 0; nt < 8; nt++) {
            const int ch = nt * 8 + lc * 2;
            float v0 = d[mt][nt][0] + b1s[ch];
            float v1 = d[mt][nt][1] + b1s[ch + 1];
            float v2 = d[mt][nt][2] + b1s[ch];
            float v3 = d[mt][nt][3] + b1s[ch + 1];
            *(float2*)&g_h[base0 + ch] = make_float2(v0, v1);
            *(float2*)&g_h[base1 + ch] = make_float2(v2, v3);
            ssum[nt * 2]     += v0 + v2;
            ssq[nt * 2]      += v0 * v0 + v2 * v2;
            ssum[nt * 2 + 1] += v1 + v3;
            ssq[nt * 2 + 1]  += v1 * v1 + v3 * v3;
        }
    }
#pragma unroll
    for (int s = 0; s < 16; s++) {
#pragma unroll
        for (int off = 4; off <= 16; off <<= 1) {
            ssum[s] += __shfl_xor_sync(0xffffffffu, ssum[s], off);
            ssq[s]  += __shfl_xor_sync(0xffffffffu, ssq[s], off);
        }
    }
    if (l < 4) {
#pragma unroll
        for (int nt = 0; nt < 8; nt++) {
            sred[w * 128 + nt * 8 + l * 2]          = ssum[nt * 2];
            sred[w * 128 + nt * 8 + l * 2 + 1]      = ssum[nt * 2 + 1];
            sred[w * 128 + 64 + nt * 8 + l * 2]     = ssq[nt * 2];
            sred[w * 128 + 64 + nt * 8 + l * 2 + 1] = ssq[nt * 2 + 1];
        }
    }
    __syncthreads();
    if (tid < 128) {
        float a = sred[tid] + sred[128 + tid] + sred[256 + tid] + sred[384 + tid];
        int slot = (blockIdx.x + (blockIdx.y << 2) + blockIdx.z) & 31;
        atomicAdd(&g_stats[slot * 128 + tid], a);
    }
}

// ------------------------- K2: finalize BN2d ------------------------------
__global__ void k2_bn2d(const float* __restrict__ g1, const float* __restrict__ be1) {
    int c = threadIdx.x;  // 64
    float s = 0.f, q = 0.f;
    for (int sl = 0; sl < 32; sl++) { s += g_stats[sl * 128 + c]; q += g_stats[sl * 128 + 64 + c]; }
    const float invcnt = 1.0f / (float)((size_t)BB * NN * NN);
    float m = s * invcnt;
    float v = q * invcnt - m * m;
    float a = g1[c] / sqrtf(v + 1e-5f);
    g_bn[c] = a;
    g_bn[64 + c] = be1[c] - m * a;
}

// ------------------------- K3: scores + softmax -> g_A --------------------
// grid (512 i, 4 b), 256 threads. 16 lanes cooperate per j-row (coalesced h).
__global__ __launch_bounds__(256) void k3_softmax(const int* __restrict__ A_init,
                                                  const float* __restrict__ W2,
                                                  const float* __restrict__ b2) {
    __shared__ float sA[512];
    __shared__ float sa[64], sc[64], sw[64];
    __shared__ float red[16];

    const int tid = threadIdx.x;
    const int i = blockIdx.x, b = blockIdx.y;
    if (tid < 64) { sa[tid] = g_bn[tid]; sc[tid] = g_bn[64 + tid]; sw[tid] = W2[tid]; }
    __syncthreads();

    const int w = tid >> 5, l = tid & 31, g = l >> 4, q = l & 15;
    const float* hrow = g_h + ((size_t)b * NN + i) * NN * CMID;
    const int* arow = A_init + ((size_t)b * NN + i) * NN;
    const float b2v = b2[0];
    const int o = q * 4;
    const float a0 = sa[o], a1 = sa[o + 1], a2 = sa[o + 2], a3 = sa[o + 3];
    const float c0 = sc[o], c1 = sc[o + 1], c2 = sc[o + 2], c3 = sc[o + 3];
    const float w0 = sw[o], w1 = sw[o + 1], w2v = sw[o + 2], w3 = sw[o + 3];

#pragma unroll 4
    for (int t = 0; t < 32; t++) {
        int j = t * 16 + w * 2 + g;
        float4 h4 = *(const float4*)(hrow + (size_t)j * CMID + o);
        float z0 = h4.x * a0 + c0, z1 = h4.y * a1 + c1;
        float z2 = h4.z * a2 + c2, z3 = h4.w * a3 + c3;
        z0 = fmaxf(z0, 0.f) + 0.01f * fminf(z0, 0.f);
        z1 = fmaxf(z1, 0.f) + 0.01f * fminf(z1, 0.f);
        z2 = fmaxf(z2, 0.f) + 0.01f * fminf(z2, 0.f);
        z3 = fmaxf(z3, 0.f) + 0.01f * fminf(z3, 0.f);
        float p = z0 * w0 + z1 * w1 + z2 * w2v + z3 * w3;
        p += __shfl_down_sync(0xffffffffu, p, 8, 16);
        p += __shfl_down_sync(0xffffffffu, p, 4, 16);
        p += __shfl_down_sync(0xffffffffu, p, 2, 16);
        p += __shfl_down_sync(0xffffffffu, p, 1, 16);
        if (q == 0) sA[j] = (arow[j] > 0) ? (p + b2v) : -9e15f;
    }
    __syncthreads();

    float m0 = fmaxf(sA[tid], sA[tid + 256]);
#pragma unroll
    for (int off = 16; off > 0; off >>= 1) m0 = fmaxf(m0, __shfl_xor_sync(0xffffffffu, m0, off));
    if (l == 0) red[w] = m0;
    __syncthreads();
    float m = red[0];
#pragma unroll
    for (int k = 1; k < 8; k++) m = fmaxf(m, red[k]);

    float e0 = __expf(sA[tid] - m), e1 = __expf(sA[tid + 256] - m);
    float ps = e0 + e1;
#pragma unroll
    for (int off = 16; off > 0; off >>= 1) ps += __shfl_xor_sync(0xffffffffu, ps, off);
    if (l == 0) red[8 + w] = ps;
    __syncthreads();
    float tot = red[8] + red[9] + red[10] + red[11] + red[12] + red[13] + red[14] + red[15];
    float inv = 1.0f / tot;

    const size_t rowbase = ((size_t)b * NN + i) * NN;
    g_A[rowbase + tid]       = e0 * inv;
    g_A[rowbase + 256 + tid] = e1 * inv;
}

// ------------------------- K3b: y0 = A @ x (tiled) ------------------------
// grid (16 it, 4 b), 256 threads; block covers 32 i-rows x 128 channels.
__global__ __launch_bounds__(256) void k3b_agg(const float* __restrict__ x) {
    __shared__ float xs[64][128];
    __shared__ float as[32][64];
    const int tid = threadIdx.x;
    const int it = blockIdx.x, b = blockIdx.y;
    const int i0 = it * 32;
    const int c = tid & 127, half = tid >> 7;

    float acc[16];
#pragma unroll
    for (int r = 0; r < 16; r++) acc[r] = 0.f;

    for (int jc = 0; jc < 512; jc += 64) {
        __syncthreads();
        // stage x chunk [64 j][128 c]
        for (int idx = tid * 4; idx < 64 * 128; idx += 256 * 4) {
            int r = idx >> 7, cc = idx & 127;
            *(float4*)&xs[r][cc] = *(const float4*)&x[((size_t)b * NN + jc + r) * CIN + cc];
        }
        // stage A chunk [32 i][64 j]
        for (int idx = tid * 4; idx < 32 * 64; idx += 256 * 4) {
            int r = idx >> 6, j = idx & 63;
            *(float4*)&as[r][j] = *(const float4*)&g_A[((size_t)b * NN + i0 + r) * NN + jc + j];
        }
        __syncthreads();

        for (int j = 0; j < 64; j += 4) {
            float x0 = xs[j][c], x1 = xs[j + 1][c], x2 = xs[j + 2][c], x3 = xs[j + 3][c];
#pragma unroll
            for (int r = 0; r < 16; r++) {
                float4 a4 = *(const float4*)&as[half * 16 + r][j];
                acc[r] += a4.x * x0 + a4.y * x1 + a4.z * x2 + a4.w * x3;
            }
        }
    }
#pragma unroll
    for (int r = 0; r < 16; r++)
        g_y0[((size_t)b * NN + i0 + half * 16 + r) * CIN + c] = acc[r];
}

// ------------------------- K4: y1 = y0 @ Wg^T + bg, + BN1d stats ----------
__global__ __launch_bounds__(256) void k4_fc_g(const float* __restrict__ Wg,
                                               const float* __restrict__ bg) {
    __shared__ float ys[32][129];
    __shared__ float s0[128], q0[128];
    const int tid = threadIdx.x;
    const int rb = blockIdx.x;
    for (int idx = tid; idx < 32 * 128; idx += 256) {
        int r = idx >> 7, c = idx & 127;
        ys[r][c] = g_y0[(size_t)(rb * 32 + r) * 128 + c];
    }
    __syncthreads();
    const int c = tid & 127, half = tid >> 7;
    float acc[16];
    const float bgv = bg[c];
#pragma unroll
    for (int r = 0; r < 16; r++) acc[r] = bgv;
    const float* wrow = Wg + (size_t)c * 128;
    for (int k = 0; k < 128; k++) {
        float w = __ldg(&wrow[k]);
#pragma unroll
        for (int r = 0; r < 16; r++) acc[r] += ys[half * 16 + r][k] * w;
    }
    float s = 0.f, q = 0.f;
#pragma unroll
    for (int r = 0; r < 16; r++) {
        float v = acc[r];
        s += v; q += v * v;
        g_y1[(size_t)(rb * 32 + half * 16 + r) * 128 + c] = v;
    }
    if (half == 0) { s0[c] = s; q0[c] = q; }
    __syncthreads();
    if (half == 1) {
        atomicAdd(&g_statsg[c], s + s0[c]);
        atomicAdd(&g_statsg[128 + c], q + q0[c]);
    }
}

// ------------------------- K5: finalize BN1d ------------------------------
__global__ void k5_bn1d(const float* __restrict__ gg, const float* __restrict__ beg) {
    int c = threadIdx.x;  // 128
    const float invcnt = 1.0f / (float)(BB * NN);
    float m = g_statsg[c] * invcnt;
    float v = g_statsg[128 + c] * invcnt - m * m;
    float a = gg[c] / sqrtf(v + 1e-5f);
    g_bng[c] = a;
    g_bng[128 + c] = beg[c] - m * a;
}

// ------------------------- K6: out = [x, lrelu(BN(y1))] @ Wt^T + bt -------
__global__ __launch_bounds__(256) void k6_trans(const float* __restrict__ x,
                                                const float* __restrict__ Wt,
                                                const float* __restrict__ bt,
                                                float* __restrict__ out) {
    __shared__ float zs[32][257];
    const int tid = threadIdx.x;
    const int rb = blockIdx.x;
    for (int idx = tid; idx < 32 * 256; idx += 256) {
        int r = idx >> 8, k = idx & 255;
        int row = rb * 32 + r;
        float v;
        if (k < 128) {
            v = x[(size_t)row * 128 + k];
        } else {
            int hch = k - 128;
            float y = g_y1[(size_t)row * 128 + hch];
            y = y * g_bng[hch] + g_bng[128 + hch];
            v = y > 0.f ? y : 0.01f * y;
        }
        zs[r][k] = v;
    }
    __syncthreads();
    const int c = tid & 127, half = tid >> 7;
    float acc[16];
    const float btv = bt[c];
#pragma unroll
    for (int r = 0; r < 16; r++) acc[r] = btv;
    const float* wrow = Wt + (size_t)c * 256;
    for (int k = 0; k < 256; k++) {
        float w = __ldg(&wrow[k]);
#pragma unroll
        for (int r = 0; r < 16; r++) acc[r] += zs[half * 16 + r][k] * w;
    }
#pragma unroll
    for (int r = 0; r < 16; r++)
        out[(size_t)(rb * 32 + half * 16 + r) * 128 + c] = acc[r];
}

// ------------------------- launch -----------------------------------------
extern "C" void kernel_launch(void* const* d_in, const int* in_sizes, int n_in,
                              void* d_out, int out_size) {
    const float* x      = (const float*)d_in[0];
    const int*   A_init = (const int*)d_in[1];
    const float* W1     = (const float*)d_in[2];
    const float* b1     = (const float*)d_in[3];
    const float* g1     = (const float*)d_in[4];
    const float* be1    = (const float*)d_in[5];
    const float* W2     = (const float*)d_in[6];
    const float* b2     = (const float*)d_in[7];
    const float* Wg     = (const float*)d_in[8];
    const float* bg     = (const float*)d_in[9];
    const float* gg     = (const float*)d_in[10];
    const float* beg    = (const float*)d_in[11];
    const float* Wt     = (const float*)d_in[12];
    const float* bt     = (const float*)d_in[13];
    float* out = (float*)d_out;

    cudaFuncSetAttribute(k1_pair_gemm, cudaFuncAttributeMaxDynamicSharedMemorySize, K1_SMEM);

    k0_zero<<<1, 256>>>();
    dim3 g1grid(4, 512, 4);
    k1_pair_gemm<<<g1grid, 128, K1_SMEM>>>(x, W1, b1);
    k2_bn2d<<<1, 64>>>(g1, be1);
    dim3 g3grid(512, 4);
    k3_softmax<<<g3grid, 256>>>(A_init, W2, b2);
    dim3 g3bgrid(16, 4);
    k3b_agg<<<g3bgrid, 256>>>(x);
    k4_fc_g<<<64, 256>>>(Wg, bg);
    k5_bn1d<<<1, 128>>>(gg, beg);
    k6_trans<<<64, 256>>>(x, Wt, bt, out);
}

// round 6
// speedup vs baseline: 2.5454x; 1.3218x over previous
#include <cuda_runtime.h>
#include <cuda_bf16.h>
#include <cuda_fp16.h>
#include <math.h>
#include <cstdint>

#define BB   4
#define NN   512
#define CIN  128
#define CMID 64

// ------------------------- scratch (device globals) ------------------------
__device__ __half g_h[(size_t)BB * NN * NN * CMID];  // 128 MB h (fp16)
__device__ float g_A[(size_t)BB * NN * NN];          // 4 MB softmax probs
__device__ float g_stats[32 * 128];
__device__ float g_bn[2 * CMID];
__device__ float g_y0[BB * NN * CIN];
__device__ float g_y1[BB * NN * 128];
__device__ float g_statsg[2 * 128];
__device__ float g_bng[2 * 128];

// ------------------------- mma.sync bf16 helpers ---------------------------
__device__ __forceinline__ void mma_bf16(float* d, const uint32_t* a,
                                         uint32_t b0, uint32_t b1) {
    asm volatile(
        "mma.sync.aligned.m16n8k16.row.col.f32.bf16.bf16.f32 "
        "{%0,%1,%2,%3}, {%4,%5,%6,%7}, {%8,%9}, {%0,%1,%2,%3};"
        : "+f"(d[0]), "+f"(d[1]), "+f"(d[2]), "+f"(d[3])
        : "r"(a[0]), "r"(a[1]), "r"(a[2]), "r"(a[3]), "r"(b0), "r"(b1));
}
__device__ __forceinline__ void split2(float v0, float v1, uint32_t &hi, uint32_t &lo) {
    float h0 = __bfloat162float(__float2bfloat16(v0));
    float h1 = __bfloat162float(__float2bfloat16(v1));
    asm("cvt.rn.bf16x2.f32 %0, %1, %2;" : "=r"(hi) : "f"(h1), "f"(h0));
    float l0 = v0 - h0, l1 = v1 - h1;
    asm("cvt.rn.bf16x2.f32 %0, %1, %2;" : "=r"(lo) : "f"(l1), "f"(l0));
}

// ------------------------- K0: zero stat accumulators ---------------------
__global__ void k0_zero() {
    int t = threadIdx.x;
    for (int i = t; i < 32 * 128; i += 256) g_stats[i] = 0.f;
    if (t < 256) g_statsg[t] = 0.f;
}

// ------------------------- K1: symmetric pairwise GEMM (bf16 3x-split) ----
// grid (4 jt, 512 i, 4 b); blocks with jt < i>>7 exit (symmetry).
// Block: fixed i; M = 128 j, N = 64 ch, K = 128. Writes h[i,j] (j>=i) and
// mirror h[j,i] (j>i); BN stats weighted 2/1/0.
#define OFF_XI   0
#define OFF_B1   512
#define OFF_SRED 768
#define OFF_XJS  2816
#define OFF_WHI  21248
#define OFF_WLO  37632
#define K1_SMEM  54016

__global__ __launch_bounds__(128) void k1_pair_gemm(const float* __restrict__ x,
                                                    const float* __restrict__ W1,
                                                    const float* __restrict__ b1) {
    const int jt = blockIdx.x, i = blockIdx.y, b = blockIdx.z;
    if (jt < (i >> 7)) return;   // symmetric half skipped

    extern __shared__ char smem[];
    float*    xi_s = (float*)(smem + OFF_XI);
    float*    b1s  = (float*)(smem + OFF_B1);
    float*    sred = (float*)(smem + OFF_SRED);
    float*    xjS  = (float*)(smem + OFF_XJS);
    uint32_t* Whi  = (uint32_t*)(smem + OFF_WHI);
    uint32_t* Wlo  = (uint32_t*)(smem + OFF_WLO);

    const int tid = threadIdx.x;
    const int w = tid >> 5, l = tid & 31;
    const int lr = l >> 2, lc = l & 3;
    const int j0 = jt * 128;
    const float* xb = x + (size_t)b * NN * CIN;

    xi_s[tid] = xb[(size_t)i * CIN + tid];
    if (tid < 64) b1s[tid] = b1[tid];

    for (int idx = tid; idx < 4096; idx += 128) {
        int o = idx >> 6, kp = idx & 63;
        float2 v = *(const float2*)&W1[o * 128 + kp * 2];
        uint32_t hi, lo;
        split2(v.x, v.y, hi, lo);
        int off = o * 64 + (kp ^ ((o & 7) << 2));
        Whi[off] = hi;
        Wlo[off] = lo;
    }

    float d[2][8][4];
#pragma unroll
    for (int mt = 0; mt < 2; mt++)
#pragma unroll
        for (int nt = 0; nt < 8; nt++)
#pragma unroll
            for (int r = 0; r < 4; r++) d[mt][nt][r] = 0.f;

    for (int kc = 0; kc < 128; kc += 32) {
        __syncthreads();
        for (int it = 0; it < 32; it++) {
            int row = it * 4 + (tid >> 5);
            int kk = tid & 31;
            xjS[row * 36 + kk] = xb[(size_t)(j0 + row) * CIN + kc + kk];
        }
        __syncthreads();

#pragma unroll
        for (int ks = 0; ks < 2; ks++) {
            const int k0 = ks * 16;
            const int kg = kc + k0;
            const float2 xv0 = *(const float2*)&xi_s[kg + 2 * lc];
            const float2 xv1 = *(const float2*)&xi_s[kg + 8 + 2 * lc];

            uint32_t ahi[2][4], alo[2][4];
#pragma unroll
            for (int mt = 0; mt < 2; mt++) {
                const int rbase = (w * 32 + mt * 16 + lr) * 36 + k0 + 2 * lc;
                float2 j00 = *(const float2*)&xjS[rbase];
                float2 j10 = *(const float2*)&xjS[rbase + 8 * 36];
                float2 j01 = *(const float2*)&xjS[rbase + 8];
                float2 j11 = *(const float2*)&xjS[rbase + 8 * 36 + 8];
                split2(fabsf(xv0.x - j00.x), fabsf(xv0.y - j00.y), ahi[mt][0], alo[mt][0]);
                split2(fabsf(xv0.x - j10.x), fabsf(xv0.y - j10.y), ahi[mt][1], alo[mt][1]);
                split2(fabsf(xv1.x - j01.x), fabsf(xv1.y - j01.y), ahi[mt][2], alo[mt][2]);
                split2(fabsf(xv1.x - j11.x), fabsf(xv1.y - j11.y), ahi[mt][3], alo[mt][3]);
            }

            const int kgp = kg >> 1;
            const int swz = lr << 2;
            const int c0 = (kgp + lc) ^ swz;
            const int c1 = (kgp + 4 + lc) ^ swz;
#pragma unroll
            for (int nt = 0; nt < 8; nt++) {
                const int ob = (nt * 8 + lr) * 64;
                uint32_t bh0 = Whi[ob + c0];
                uint32_t bh1 = Whi[ob + c1];
                uint32_t bl0 = Wlo[ob + c0];
                uint32_t bl1 = Wlo[ob + c1];
#pragma unroll
                for (int mt = 0; mt < 2; mt++) {
                    mma_bf16(d[mt][nt], ahi[mt], bh0, bh1);
                    mma_bf16(d[mt][nt], ahi[mt], bl0, bl1);
                    mma_bf16(d[mt][nt], alo[mt], bh0, bh1);
                }
            }
        }
    }

    // ---- epilogue: bias, symmetric stores (fp16), weighted stats
    float ssum[16], ssq[16];
#pragma unroll
    for (int s = 0; s < 16; s++) { ssum[s] = 0.f; ssq[s] = 0.f; }

    const size_t bOff = (size_t)b * NN;
#pragma unroll
    for (int mt = 0; mt < 2; mt++) {
        const int jrow0 = j0 + w * 32 + mt * 16 + lr;
        const int jrow1 = jrow0 + 8;
        const float w0f = (jrow0 > i) ? 2.f : (jrow0 == i ? 1.f : 0.f);
        const float w1f = (jrow1 > i) ? 2.f : (jrow1 == i ? 1.f : 0.f);
        const size_t dir0 = ((bOff + i) * NN + jrow0) * CMID;
        const size_t dir1 = ((bOff + i) * NN + jrow1) * CMID;
        const size_t mir0 = ((bOff + jrow0) * NN + i) * CMID;
        const size_t mir1 = ((bOff + jrow1) * NN + i) * CMID;
#pragma unroll
        for (int nt = 0; nt < 8; nt++) {
            const int ch = nt * 8 + lc * 2;
            float v0 = d[mt][nt][0] + b1s[ch];
            float v1 = d[mt][nt][1] + b1s[ch + 1];
            float v2 = d[mt][nt][2] + b1s[ch];
            float v3 = d[mt][nt][3] + b1s[ch + 1];
            __half2 p01 = __floats2half2_rn(v0, v1);
            __half2 p23 = __floats2half2_rn(v2, v3);
            if (jrow0 >= i) *(__half2*)&g_h[dir0 + ch] = p01;
            if (jrow1 >= i) *(__half2*)&g_h[dir1 + ch] = p23;
            if (jrow0 > i)  *(__half2*)&g_h[mir0 + ch] = p01;
            if (jrow1 > i)  *(__half2*)&g_h[mir1 + ch] = p23;
            ssum[nt * 2]     += w0f * v0 + w1f * v2;
            ssq[nt * 2]      += w0f * v0 * v0 + w1f * v2 * v2;
            ssum[nt * 2 + 1] += w0f * v1 + w1f * v3;
            ssq[nt * 2 + 1]  += w0f * v1 * v1 + w1f * v3 * v3;
        }
    }
#pragma unroll
    for (int s = 0; s < 16; s++) {
#pragma unroll
        for (int off = 4; off <= 16; off <<= 1) {
            ssum[s] += __shfl_xor_sync(0xffffffffu, ssum[s], off);
            ssq[s]  += __shfl_xor_sync(0xffffffffu, ssq[s], off);
        }
    }
    if (l < 4) {
#pragma unroll
        for (int nt = 0; nt < 8; nt++) {
            sred[w * 128 + nt * 8 + l * 2]          = ssum[nt * 2];
            sred[w * 128 + nt * 8 + l * 2 + 1]      = ssum[nt * 2 + 1];
            sred[w * 128 + 64 + nt * 8 + l * 2]     = ssq[nt * 2];
            sred[w * 128 + 64 + nt * 8 + l * 2 + 1] = ssq[nt * 2 + 1];
        }
    }
    __syncthreads();
    if (tid < 128) {
        float a = sred[tid] + sred[128 + tid] + sred[256 + tid] + sred[384 + tid];
        int slot = (blockIdx.x + (blockIdx.y << 2) + blockIdx.z) & 31;
        atomicAdd(&g_stats[slot * 128 + tid], a);
    }
}

// ------------------------- K2: finalize BN2d ------------------------------
__global__ void k2_bn2d(const float* __restrict__ g1, const float* __restrict__ be1) {
    int c = threadIdx.x;  // 64
    float s = 0.f, q = 0.f;
    for (int sl = 0; sl < 32; sl++) { s += g_stats[sl * 128 + c]; q += g_stats[sl * 128 + 64 + c]; }
    const float invcnt = 1.0f / (float)((size_t)BB * NN * NN);
    float m = s * invcnt;
    float v = q * invcnt - m * m;
    float a = g1[c] / sqrtf(v + 1e-5f);
    g_bn[c] = a;
    g_bn[64 + c] = be1[c] - m * a;
}

// ------------------------- K3: scores + softmax -> g_A (fp16 h) -----------
// grid (512 i, 4 b), 256 threads. 8 lanes cooperate per j-row (16B loads).
__global__ __launch_bounds__(256) void k3_softmax(const int* __restrict__ A_init,
                                                  const float* __restrict__ W2,
                                                  const float* __restrict__ b2) {
    __shared__ float sA[512];
    __shared__ float sa[64], sc[64], sw[64];
    __shared__ float red[16];

    const int tid = threadIdx.x;
    const int i = blockIdx.x, b = blockIdx.y;
    if (tid < 64) { sa[tid] = g_bn[tid]; sc[tid] = g_bn[64 + tid]; sw[tid] = W2[tid]; }
    __syncthreads();

    const int w = tid >> 5, l = tid & 31, g2 = l >> 3, q = l & 7;
    const __half* hrow = g_h + ((size_t)b * NN + i) * NN * CMID;
    const int* arow = A_init + ((size_t)b * NN + i) * NN;
    const float b2v = b2[0];
    const int o = q * 8;
    float av[8], cv[8], wv[8];
#pragma unroll
    for (int k = 0; k < 8; k++) { av[k] = sa[o + k]; cv[k] = sc[o + k]; wv[k] = sw[o + k]; }

#pragma unroll 4
    for (int t = 0; t < 16; t++) {
        int j = t * 32 + w * 4 + g2;
        uint4 raw = *(const uint4*)(hrow + (size_t)j * CMID + o);
        const __half2* hp = (const __half2*)&raw;
        float p = 0.f;
#pragma unroll
        for (int k = 0; k < 4; k++) {
            float2 f = __half22float2(hp[k]);
            float z0 = f.x * av[k * 2] + cv[k * 2];
            float z1 = f.y * av[k * 2 + 1] + cv[k * 2 + 1];
            z0 = fmaxf(z0, 0.f) + 0.01f * fminf(z0, 0.f);
            z1 = fmaxf(z1, 0.f) + 0.01f * fminf(z1, 0.f);
            p += z0 * wv[k * 2] + z1 * wv[k * 2 + 1];
        }
        p += __shfl_down_sync(0xffffffffu, p, 4, 8);
        p += __shfl_down_sync(0xffffffffu, p, 2, 8);
        p += __shfl_down_sync(0xffffffffu, p, 1, 8);
        if (q == 0) sA[j] = (arow[j] > 0) ? (p + b2v) : -9e15f;
    }
    __syncthreads();

    float m0 = fmaxf(sA[tid], sA[tid + 256]);
#pragma unroll
    for (int off = 16; off > 0; off >>= 1) m0 = fmaxf(m0, __shfl_xor_sync(0xffffffffu, m0, off));
    if (l == 0) red[w] = m0;
    __syncthreads();
    float m = red[0];
#pragma unroll
    for (int k = 1; k < 8; k++) m = fmaxf(m, red[k]);

    float e0 = __expf(sA[tid] - m), e1 = __expf(sA[tid + 256] - m);
    float ps = e0 + e1;
#pragma unroll
    for (int off = 16; off > 0; off >>= 1) ps += __shfl_xor_sync(0xffffffffu, ps, off);
    if (l == 0) red[8 + w] = ps;
    __syncthreads();
    float tot = red[8] + red[9] + red[10] + red[11] + red[12] + red[13] + red[14] + red[15];
    float inv = 1.0f / tot;

    const size_t rowbase = ((size_t)b * NN + i) * NN;
    g_A[rowbase + tid]       = e0 * inv;
    g_A[rowbase + 256 + tid] = e1 * inv;
}

// ------------------------- K3b: y0 = A @ x (tiled) ------------------------
__global__ __launch_bounds__(256) void k3b_agg(const float* __restrict__ x) {
    __shared__ float xs[64][128];
    __shared__ float as[32][64];
    const int tid = threadIdx.x;
    const int it = blockIdx.x, b = blockIdx.y;
    const int i0 = it * 32;
    const int c = tid & 127, half = tid >> 7;

    float acc[16];
#pragma unroll
    for (int r = 0; r < 16; r++) acc[r] = 0.f;

    for (int jc = 0; jc < 512; jc += 64) {
        __syncthreads();
        for (int idx = tid * 4; idx < 64 * 128; idx += 256 * 4) {
            int r = idx >> 7, cc = idx & 127;
            *(float4*)&xs[r][cc] = *(const float4*)&x[((size_t)b * NN + jc + r) * CIN + cc];
        }
        for (int idx = tid * 4; idx < 32 * 64; idx += 256 * 4) {
            int r = idx >> 6, j = idx & 63;
            *(float4*)&as[r][j] = *(const float4*)&g_A[((size_t)b * NN + i0 + r) * NN + jc + j];
        }
        __syncthreads();

        for (int j = 0; j < 64; j += 4) {
            float x0 = xs[j][c], x1 = xs[j + 1][c], x2 = xs[j + 2][c], x3 = xs[j + 3][c];
#pragma unroll
            for (int r = 0; r < 16; r++) {
                float4 a4 = *(const float4*)&as[half * 16 + r][j];
                acc[r] += a4.x * x0 + a4.y * x1 + a4.z * x2 + a4.w * x3;
            }
        }
    }
#pragma unroll
    for (int r = 0; r < 16; r++)
        g_y0[((size_t)b * NN + i0 + half * 16 + r) * CIN + c] = acc[r];
}

// ------------------------- K4: y1 = y0 @ Wg^T + bg, + BN1d stats ----------
__global__ __launch_bounds__(256) void k4_fc_g(const float* __restrict__ Wg,
                                               const float* __restrict__ bg) {
    __shared__ float ys[32][129];
    __shared__ float s0[128], q0[128];
    const int tid = threadIdx.x;
    const int rb = blockIdx.x;
    for (int idx = tid; idx < 32 * 128; idx += 256) {
        int r = idx >> 7, c = idx & 127;
        ys[r][c] = g_y0[(size_t)(rb * 32 + r) * 128 + c];
    }
    __syncthreads();
    const int c = tid & 127, half = tid >> 7;
    float acc[16];
    const float bgv = bg[c];
#pragma unroll
    for (int r = 0; r < 16; r++) acc[r] = bgv;
    const float* wrow = Wg + (size_t)c * 128;
    for (int k = 0; k < 128; k++) {
        float w = __ldg(&wrow[k]);
#pragma unroll
        for (int r = 0; r < 16; r++) acc[r] += ys[half * 16 + r][k] * w;
    }
    float s = 0.f, q = 0.f;
#pragma unroll
    for (int r = 0; r < 16; r++) {
        float v = acc[r];
        s += v; q += v * v;
        g_y1[(size_t)(rb * 32 + half * 16 + r) * 128 + c] = v;
    }
    if (half == 0) { s0[c] = s; q0[c] = q; }
    __syncthreads();
    if (half == 1) {
        atomicAdd(&g_statsg[c], s + s0[c]);
        atomicAdd(&g_statsg[128 + c], q + q0[c]);
    }
}

// ------------------------- K5: finalize BN1d ------------------------------
__global__ void k5_bn1d(const float* __restrict__ gg, const float* __restrict__ beg) {
    int c = threadIdx.x;  // 128
    const float invcnt = 1.0f / (float)(BB * NN);
    float m = g_statsg[c] * invcnt;
    float v = g_statsg[128 + c] * invcnt - m * m;
    float a = gg[c] / sqrtf(v + 1e-5f);
    g_bng[c] = a;
    g_bng[128 + c] = beg[c] - m * a;
}

// ------------------------- K6: out = [x, lrelu(BN(y1))] @ Wt^T + bt -------
__global__ __launch_bounds__(256) void k6_trans(const float* __restrict__ x,
                                                const float* __restrict__ Wt,
                                                const float* __restrict__ bt,
                                                float* __restrict__ out) {
    __shared__ float zs[32][257];
    const int tid = threadIdx.x;
    const int rb = blockIdx.x;
    for (int idx = tid; idx < 32 * 256; idx += 256) {
        int r = idx >> 8, k = idx & 255;
        int row = rb * 32 + r;
        float v;
        if (k < 128) {
            v = x[(size_t)row * 128 + k];
        } else {
            int hch = k - 128;
            float y = g_y1[(size_t)row * 128 + hch];
            y = y * g_bng[hch] + g_bng[128 + hch];
            v = y > 0.f ? y : 0.01f * y;
        }
        zs[r][k] = v;
    }
    __syncthreads();
    const int c = tid & 127, half = tid >> 7;
    float acc[16];
    const float btv = bt[c];
#pragma unroll
    for (int r = 0; r < 16; r++) acc[r] = btv;
    const float* wrow = Wt + (size_t)c * 256;
    for (int k = 0; k < 256; k++) {
        float w = __ldg(&wrow[k]);
#pragma unroll
        for (int r = 0; r < 16; r++) acc[r] += zs[half * 16 + r][k] * w;
    }
#pragma unroll
    for (int r = 0; r < 16; r++)
        out[(size_t)(rb * 32 + half * 16 + r) * 128 + c] = acc[r];
}

// ------------------------- launch -----------------------------------------
extern "C" void kernel_launch(void* const* d_in, const int* in_sizes, int n_in,
                              void* d_out, int out_size) {
    const float* x      = (const float*)d_in[0];
    const int*   A_init = (const int*)d_in[1];
    const float* W1     = (const float*)d_in[2];
    const float* b1     = (const float*)d_in[3];
    const float* g1     = (const float*)d_in[4];
    const float* be1    = (const float*)d_in[5];
    const float* W2     = (const float*)d_in[6];
    const float* b2     = (const float*)d_in[7];
    const float* Wg     = (const float*)d_in[8];
    const float* bg     = (const float*)d_in[9];
    const float* gg     = (const float*)d_in[10];
    const float* beg    = (const float*)d_in[11];
    const float* Wt     = (const float*)d_in[12];
    const float* bt     = (const float*)d_in[13];
    float* out = (float*)d_out;

    cudaFuncSetAttribute(k1_pair_gemm, cudaFuncAttributeMaxDynamicSharedMemorySize, K1_SMEM);

    k0_zero<<<1, 256>>>();
    dim3 g1grid(4, 512, 4);
    k1_pair_gemm<<<g1grid, 128, K1_SMEM>>>(x, W1, b1);
    k2_bn2d<<<1, 64>>>(g1, be1);
    dim3 g3grid(512, 4);
    k3_softmax<<<g3grid, 256>>>(A_init, W2, b2);
    dim3 g3bgrid(16, 4);
    k3b_agg<<<g3bgrid, 256>>>(x);
    k4_fc_g<<<64, 256>>>(Wg, bg);
    k5_bn1d<<<1, 128>>>(gg, beg);
    k6_trans<<<64, 256>>>(x, Wt, bt, out);
}